// round 7
// baseline (speedup 1.0000x reference)
#include <cuda_runtime.h>
#include <cuda_bf16.h>
#include <cstdint>
#include <math.h>

#define B_N 32768
#define D_N 512
#define K_N 1024
#define L_N 4

// smem offsets (bytes). Rows padded to 80B -> conflict-free ldmatrix.
// A tiles: 128 rows x 80B = 10240 per hi/lo, double buffered.
// B tiles:  64 rows x 80B =  5120 per hi/lo, double buffered.
#define SA0_HI 0
#define SA0_LO 10240
#define SA1_HI 20480
#define SA1_LO 30720
#define SB0_HI 40960
#define SB0_LO 46080
#define SB1_HI 51200
#define SB1_LO 56320
#define SMISC  61440
#define SMEM_SZ 61952

__device__ float         g_zr   [(size_t)B_N * D_N];
__device__ __nv_bfloat16 g_zr_hi[(size_t)B_N * D_N];
__device__ __nv_bfloat16 g_zr_lo[(size_t)B_N * D_N];
__device__ __nv_bfloat16 g_cb_hi[(size_t)L_N * K_N * D_N];
__device__ __nv_bfloat16 g_cb_lo[(size_t)L_N * K_N * D_N];
__device__ __nv_bfloat16 g_cbT_hi[(size_t)L_N * D_N * K_N];
__device__ __nv_bfloat16 g_cbT_lo[(size_t)L_N * D_N * K_N];
__device__ __nv_bfloat16 g_W_hi[D_N * D_N];
__device__ __nv_bfloat16 g_W_lo[D_N * D_N];
__device__ float         g_csq[L_N * K_N];
__device__ __nv_bfloat16 g_Eh[(size_t)B_N * K_N];
__device__ __nv_bfloat16 g_El[(size_t)B_N * K_N];
__device__ float         g_Spart[(size_t)32 * B_N];

// ---------------- asm helpers ----------------
__device__ __forceinline__ uint32_t smem_u32(const void* p) {
    uint32_t a;
    asm("{ .reg .u64 t; cvta.to.shared.u64 t, %1; cvt.u32.u64 %0, t; }" : "=r"(a) : "l"(p));
    return a;
}
#define LDSM4(R0,R1,R2,R3,ADDR) \
    asm volatile("ldmatrix.sync.aligned.m8n8.x4.shared.b16 {%0,%1,%2,%3}, [%4];" \
        : "=r"(R0),"=r"(R1),"=r"(R2),"=r"(R3) : "r"(ADDR))
#define MMA(ACC,A,B0,B1) \
    asm volatile("mma.sync.aligned.m16n8k16.row.col.f32.bf16.bf16.f32 " \
        "{%0,%1,%2,%3},{%4,%5,%6,%7},{%8,%9},{%0,%1,%2,%3};" \
        : "+f"((ACC)[0]),"+f"((ACC)[1]),"+f"((ACC)[2]),"+f"((ACC)[3]) \
        : "r"((A)[0]),"r"((A)[1]),"r"((A)[2]),"r"((A)[3]),"r"(B0),"r"(B1))
#define CP16(DST,SRC) \
    asm volatile("cp.async.cg.shared.global [%0], [%1], 16;" :: "r"(DST), "l"(SRC))
#define CP_COMMIT() asm volatile("cp.async.commit_group;" ::: "memory")
#define CP_WAIT1()  asm volatile("cp.async.wait_group 1;" ::: "memory")
#define CP_WAIT0()  asm volatile("cp.async.wait_group 0;" ::: "memory")

__device__ __forceinline__ uint32_t pack2(float a, float b) {
    __nv_bfloat162 t = __floats2bfloat162_rn(a, b);
    return *(uint32_t*)&t;
}
__device__ __forceinline__ float2 unpack2(uint32_t u) {
    __nv_bfloat162 t = *(__nv_bfloat162*)&u;
    return make_float2(__bfloat162float(t.x), __bfloat162float(t.y));
}
__device__ __forceinline__ float bfr(float x) {
    return __bfloat162float(__float2bfloat16_rn(x));
}

// 3-pass bf16-split MMA over one K=32 chunk. A hi at aBase (+10240 lo),
// B hi at bBase (+5120 lo).
__device__ __forceinline__ void compute_chunk(float acc[2][4][4], uint32_t smb,
                                              uint32_t aBase, uint32_t bBase,
                                              int wy, int wx, int lane) {
    #pragma unroll
    for (int ks = 0; ks < 2; ks++) {
        uint32_t aH[2][4], aL[2][4], bH[4][2], bL[4][2];
        #pragma unroll
        for (int i = 0; i < 2; i++) {
            uint32_t ar = smb + aBase + (uint32_t)(wy*32 + i*16 + (lane & 15))*80
                          + ks*32 + ((lane >> 4) << 4);
            LDSM4(aH[i][0],aH[i][1],aH[i][2],aH[i][3], ar);
            LDSM4(aL[i][0],aL[i][1],aL[i][2],aL[i][3], ar + 10240);
        }
        #pragma unroll
        for (int jj = 0; jj < 2; jj++) {
            uint32_t br = smb + bBase + (uint32_t)(wx*32 + jj*16 + (lane & 15))*80
                          + ks*32 + ((lane >> 4) << 4);
            uint32_t r0,r1,r2,r3;
            LDSM4(r0,r1,r2,r3, br);
            bH[jj*2][0]=r0; bH[jj*2][1]=r2; bH[jj*2+1][0]=r1; bH[jj*2+1][1]=r3;
            LDSM4(r0,r1,r2,r3, br + 5120);
            bL[jj*2][0]=r0; bL[jj*2][1]=r2; bL[jj*2+1][0]=r1; bL[jj*2+1][1]=r3;
        }
        #pragma unroll
        for (int i = 0; i < 2; i++)
            #pragma unroll
            for (int j = 0; j < 4; j++) {
                MMA(acc[i][j], aH[i], bH[j][0], bH[j][1]);
                MMA(acc[i][j], aH[i], bL[j][0], bL[j][1]);
                MMA(acc[i][j], aL[i], bH[j][0], bH[j][1]);
            }
    }
}

// B tile (64 rows x 32 cols bf16) hi+lo via cp.async
__device__ __forceinline__ void cpasync_B(uint32_t smb, uint32_t bBase,
        const __nv_bfloat16* Bh, const __nv_bfloat16* Bl,
        int nb0, int strideB, int kc, int tid) {
    int row = tid >> 2, seg = tid & 3;
    uint32_t dst = smb + bBase + (uint32_t)row*80 + seg*16;
    size_t off = (size_t)(nb0 + row) * strideB + kc*32 + seg*8;
    CP16(dst,        (const char*)(Bh + off));
    CP16(dst + 5120, (const char*)(Bl + off));
}

// A tile (128 rows x 32 cols bf16) hi+lo via cp.async
__device__ __forceinline__ void cpasync_A(uint32_t smb, uint32_t aBase,
        const __nv_bfloat16* Ah, const __nv_bfloat16* Al,
        int bm0, int strideA, int kc, int tid) {
    #pragma unroll
    for (int i = 0; i < 2; i++) {
        int idx = tid + i * 256, row = idx >> 2, seg = idx & 3;
        uint32_t dst = smb + aBase + (uint32_t)row*80 + seg*16;
        size_t off = (size_t)(bm0 + row) * strideA + kc*32 + seg*8;
        CP16(dst,         (const char*)(Ah + off));
        CP16(dst + 10240, (const char*)(Al + off));
    }
}

// ---------------- prep kernels ----------------
__global__ void csq_kernel(const float* __restrict__ cb) {
    int warp = (blockIdx.x * blockDim.x + threadIdx.x) >> 5;
    int lane = threadIdx.x & 31;
    if (warp >= L_N * K_N) return;
    const float* row = cb + (size_t)warp * D_N;
    float s = 0.f;
    #pragma unroll 4
    for (int i = lane; i < D_N; i += 32) { float v = row[i]; s += v * v; }
    #pragma unroll
    for (int o = 16; o; o >>= 1) s += __shfl_xor_sync(0xffffffffu, s, o);
    if (lane == 0) g_csq[warp] = s;
}
__global__ void split_kernel(const float* __restrict__ src,
                             __nv_bfloat16* __restrict__ hi,
                             __nv_bfloat16* __restrict__ lo, int n) {
    int i = blockIdx.x * blockDim.x + threadIdx.x;
    if (i < n) {
        float x = src[i];
        __nv_bfloat16 h = __float2bfloat16_rn(x);
        hi[i] = h;
        lo[i] = __float2bfloat16_rn(x - __bfloat162float(h));
    }
}
__global__ void tsplit_kernel(const float* __restrict__ cb) {
    __shared__ float tile[32][33];
    int l = blockIdx.z;
    int k0 = blockIdx.x * 32, d0 = blockIdx.y * 32;
    int tx = threadIdx.x, ty = threadIdx.y;
    const float* src = cb + (size_t)l * K_N * D_N;
    for (int i = ty; i < 32; i += 8)
        tile[i][tx] = src[(size_t)(k0 + i) * D_N + d0 + tx];
    __syncthreads();
    __nv_bfloat16* th = g_cbT_hi + (size_t)l * D_N * K_N;
    __nv_bfloat16* tl = g_cbT_lo + (size_t)l * D_N * K_N;
    for (int i = ty; i < 32; i += 8) {
        float x = tile[tx][i];
        __nv_bfloat16 h = __float2bfloat16_rn(x);
        size_t o = (size_t)(d0 + i) * K_N + k0 + tx;
        th[o] = h;
        tl[o] = __float2bfloat16_rn(x - __bfloat162float(h));
    }
}

// ---------------- kernel A: logits -> E (bf16 hi/lo) + partial row sums ----
// grid (16, 256). CTA tile 128(m) x 64(n), K=512. Mainloop: pure cp.async.
__global__ void __launch_bounds__(256, 2)
logits_kernel(const __nv_bfloat16* __restrict__ cbh,
              const __nv_bfloat16* __restrict__ cbl,
              const float* __restrict__ csq, const float* __restrict__ tau) {
    extern __shared__ __align__(16) char smem[];
    const uint32_t smb = smem_u32(smem);
    const int tid = threadIdx.x, lane = tid & 31, w = tid >> 5;
    const int wy = w >> 1, wx = w & 1;
    const int nb0 = blockIdx.x * 64, bm0 = blockIdx.y * 128;
    const float invtau = 1.0f / tau[0];
    float* csq_s = (float*)(smem + SMISC);
    if (tid < 64) csq_s[tid] = csq[nb0 + tid] * invtau;

    float acc[2][4][4];
    #pragma unroll
    for (int i = 0; i < 2; i++)
        #pragma unroll
        for (int j = 0; j < 4; j++)
            #pragma unroll
            for (int h = 0; h < 4; h++) acc[i][j][h] = 0.f;

    cpasync_A(smb, SA0_HI, g_zr_hi, g_zr_lo, bm0, D_N, 0, tid);
    cpasync_B(smb, SB0_HI, cbh, cbl, nb0, D_N, 0, tid);
    CP_COMMIT();

    for (int kc = 0; kc < 16; kc++) {
        __syncthreads();   // frees buffer (kc+1)&1 from compute(kc-1)
        if (kc + 1 < 16) {
            uint32_t aB = ((kc + 1) & 1) ? SA1_HI : SA0_HI;
            uint32_t bB = ((kc + 1) & 1) ? SB1_HI : SB0_HI;
            cpasync_A(smb, aB, g_zr_hi, g_zr_lo, bm0, D_N, kc + 1, tid);
            cpasync_B(smb, bB, cbh, cbl, nb0, D_N, kc + 1, tid);
            CP_COMMIT();
            CP_WAIT1();
        } else {
            CP_WAIT0();
        }
        __syncthreads();
        compute_chunk(acc, smb, (kc & 1) ? SA1_HI : SA0_HI,
                      (kc & 1) ? SB1_HI : SB0_HI, wy, wx, lane);
    }

    // epilogue: E = exp(2s/tau - csq/tau) -> bf16 hi/lo, partial row sums
    const float c2 = 2.0f * invtau;
    uint32_t* Eh32 = (uint32_t*)g_Eh;
    uint32_t* El32 = (uint32_t*)g_El;
    #pragma unroll
    for (int i = 0; i < 2; i++) {
        #pragma unroll
        for (int h = 0; h < 2; h++) {
            int r = bm0 + wy * 32 + i * 16 + (lane >> 2) + h * 8;
            float s = 0.f;
            #pragma unroll
            for (int j = 0; j < 4; j++) {
                int cl = wx * 32 + j * 8 + ((lane & 3) << 1);
                float e0 = __expf(fmaf(acc[i][j][h * 2],     c2, -csq_s[cl]));
                float e1 = __expf(fmaf(acc[i][j][h * 2 + 1], c2, -csq_s[cl + 1]));
                s += e0 + e1;
                float h0 = bfr(e0), h1 = bfr(e1);
                size_t o = ((size_t)r * K_N + nb0 + cl) >> 1;
                Eh32[o] = pack2(h0, h1);
                El32[o] = pack2(e0 - h0, e1 - h1);
            }
            s += __shfl_xor_sync(0xffffffffu, s, 1);
            s += __shfl_xor_sync(0xffffffffu, s, 2);
            if ((lane & 3) == 0)
                g_Spart[(size_t)(blockIdx.x * 2 + wx) * B_N + r] = s;
        }
    }
}

// ---------------- zsoft kernel (level GEMM B): pure cp.async mainloop ----
// grid (8, 256). z_soft = invs * (E @ cbT); writes out_z, p, residual update.
__global__ void __launch_bounds__(256, 2)
zsoft_kernel(const __nv_bfloat16* __restrict__ Bh, const __nv_bfloat16* __restrict__ Bl,
             float* __restrict__ pout, float* __restrict__ out_z) {
    extern __shared__ __align__(16) char smem[];
    const uint32_t smb = smem_u32(smem);
    const int tid = threadIdx.x, lane = tid & 31, w = tid >> 5;
    const int wy = w >> 1, wx = w & 1;
    const int nb0 = blockIdx.x * 64, bm0 = blockIdx.y * 128;
    float* invs = (float*)(smem + SMISC);
    if (tid < 128) {
        float s = 0.f;
        #pragma unroll
        for (int p = 0; p < 32; p++) s += g_Spart[(size_t)p * B_N + bm0 + tid];
        invs[tid] = 1.0f / s;
    }

    float acc[2][4][4];
    #pragma unroll
    for (int i = 0; i < 2; i++)
        #pragma unroll
        for (int j = 0; j < 4; j++)
            #pragma unroll
            for (int h = 0; h < 4; h++) acc[i][j][h] = 0.f;

    cpasync_A(smb, SA0_HI, g_Eh, g_El, bm0, K_N, 0, tid);
    cpasync_B(smb, SB0_HI, Bh, Bl, nb0, K_N, 0, tid);
    CP_COMMIT();

    for (int kc = 0; kc < 32; kc++) {
        __syncthreads();
        if (kc + 1 < 32) {
            uint32_t aB = ((kc + 1) & 1) ? SA1_HI : SA0_HI;
            uint32_t bB = ((kc + 1) & 1) ? SB1_HI : SB0_HI;
            cpasync_A(smb, aB, g_Eh, g_El, bm0, K_N, kc + 1, tid);
            cpasync_B(smb, bB, Bh, Bl, nb0, K_N, kc + 1, tid);
            CP_COMMIT();
            CP_WAIT1();
        } else {
            CP_WAIT0();
        }
        __syncthreads();
        compute_chunk(acc, smb, (kc & 1) ? SA1_HI : SA0_HI,
                      (kc & 1) ? SB1_HI : SB0_HI, wy, wx, lane);
    }

    // epilogue: z = invs*acc; out_z, residual update + bf16 re-split
    #pragma unroll
    for (int i = 0; i < 2; i++)
        #pragma unroll
        for (int j = 0; j < 4; j++)
            #pragma unroll
            for (int h = 0; h < 2; h++) {
                int rl = wy * 32 + i * 16 + (lane >> 2) + h * 8;
                int r = bm0 + rl;
                int col = nb0 + wx * 32 + j * 8 + ((lane & 3) << 1);
                size_t g = (size_t)r * D_N + col;
                float sc = invs[rl];
                float v0 = acc[i][j][h * 2] * sc, v1 = acc[i][j][h * 2 + 1] * sc;
                float2 old = *(const float2*)&g_zr[g];
                *(float2*)&out_z[g] = make_float2(v0, v1);
                float2 nr = make_float2(old.x - v0, old.y - v1);
                *(float2*)&g_zr[g] = nr;
                float hx = bfr(nr.x), hy = bfr(nr.y);
                *(uint32_t*)&g_zr_hi[g] = pack2(hx, hy);
                *(uint32_t*)&g_zr_lo[g] = pack2(nr.x - hx, nr.y - hy);
            }

    // p-write pass: this CTA owns p slice rows[bm0,+128) cols [x*128,+128)
    {
        const int c0 = blockIdx.x * 128;
        #pragma unroll
        for (int it = 0; it < 8; it++) {
            int idx = tid + it * 256;           // 0..2047
            int row = idx >> 4, cs = (idx & 15) * 8;
            size_t e = (size_t)(bm0 + row) * K_N + c0 + cs;
            uint4 hv = *(const uint4*)&g_Eh[e];
            uint4 lv = *(const uint4*)&g_El[e];
            float s = invs[row];
            float2 h0 = unpack2(hv.x), l0 = unpack2(lv.x);
            float2 h1 = unpack2(hv.y), l1 = unpack2(lv.y);
            float2 h2 = unpack2(hv.z), l2 = unpack2(lv.z);
            float2 h3 = unpack2(hv.w), l3 = unpack2(lv.w);
            float4 p0 = make_float4((h0.x + l0.x) * s, (h0.y + l0.y) * s,
                                    (h1.x + l1.x) * s, (h1.y + l1.y) * s);
            float4 p1 = make_float4((h2.x + l2.x) * s, (h2.y + l2.y) * s,
                                    (h3.x + l3.x) * s, (h3.y + l3.y) * s);
            *(float4*)&pout[e]     = p0;
            *(float4*)&pout[e + 4] = p1;
        }
    }
}

// ---------------- whiten kernel: g_zr = z0 @ W^T (register-staged A) ----
__global__ void __launch_bounds__(256, 2)
whiten_kernel(const float* __restrict__ z0,
              const __nv_bfloat16* __restrict__ Bh, const __nv_bfloat16* __restrict__ Bl) {
    extern __shared__ __align__(16) char smem[];
    const uint32_t smb = smem_u32(smem);
    const int tid = threadIdx.x, lane = tid & 31, w = tid >> 5;
    const int wy = w >> 1, wx = w & 1;
    const int nb0 = blockIdx.x * 64, bm0 = blockIdx.y * 128;

    float acc[2][4][4];
    #pragma unroll
    for (int i = 0; i < 2; i++)
        #pragma unroll
        for (int j = 0; j < 4; j++)
            #pragma unroll
            for (int h = 0; h < 4; h++) acc[i][j][h] = 0.f;

    cpasync_B(smb, SB0_HI, Bh, Bl, nb0, D_N, 0, tid);
    CP_COMMIT();
    float4 raf[4];
    #pragma unroll
    for (int i = 0; i < 4; i++) {
        int idx = tid + i * 256, row = idx >> 3, seg = idx & 7;
        raf[i] = *(const float4*)&z0[(size_t)(bm0 + row) * D_N + seg * 4];
    }

    for (int kc = 0; kc < 16; kc++) {
        __syncthreads();
        if (kc + 1 < 16) {
            cpasync_B(smb, ((kc + 1) & 1) ? SB1_HI : SB0_HI, Bh, Bl, nb0, D_N, kc + 1, tid);
            CP_COMMIT();
        }
        #pragma unroll
        for (int i = 0; i < 4; i++) {
            int idx = tid + i * 256, row = idx >> 3, seg = idx & 7;
            float4 v = raf[i];
            float hx = bfr(v.x), hy = bfr(v.y), hz = bfr(v.z), hw = bfr(v.w);
            *(uint2*)(smem + SA0_HI + row * 80 + seg * 8) =
                make_uint2(pack2(hx, hy), pack2(hz, hw));
            *(uint2*)(smem + SA0_LO + row * 80 + seg * 8) =
                make_uint2(pack2(v.x - hx, v.y - hy), pack2(v.z - hz, v.w - hw));
        }
        if (kc + 1 < 16) CP_WAIT1(); else CP_WAIT0();
        __syncthreads();
        if (kc + 1 < 16) {
            #pragma unroll
            for (int i = 0; i < 4; i++) {
                int idx = tid + i * 256, row = idx >> 3, seg = idx & 7;
                raf[i] = *(const float4*)&z0[(size_t)(bm0 + row) * D_N
                                             + (kc + 1) * 32 + seg * 4];
            }
        }
        compute_chunk(acc, smb, SA0_HI, (kc & 1) ? SB1_HI : SB0_HI, wy, wx, lane);
    }

    #pragma unroll
    for (int i = 0; i < 2; i++)
        #pragma unroll
        for (int j = 0; j < 4; j++)
            #pragma unroll
            for (int h = 0; h < 2; h++) {
                int r = bm0 + wy * 32 + i * 16 + (lane >> 2) + h * 8;
                int col = nb0 + wx * 32 + j * 8 + ((lane & 3) << 1);
                size_t g = (size_t)r * D_N + col;
                float v0 = acc[i][j][h * 2], v1 = acc[i][j][h * 2 + 1];
                *(float2*)&g_zr[g] = make_float2(v0, v1);
                float hx = bfr(v0), hy = bfr(v1);
                *(uint32_t*)&g_zr_hi[g] = pack2(hx, hy);
                *(uint32_t*)&g_zr_lo[g] = pack2(v0 - hx, v1 - hy);
            }
}

// ---------------- launch ----------------
extern "C" void kernel_launch(void* const* d_in, const int* in_sizes, int n_in,
                              void* d_out, int out_size)
{
    const float* z0   = (const float*)d_in[0];
    const float* tau  = (const float*)d_in[1];
    const float* W    = (const float*)d_in[2];
    const float* cbks = (const float*)d_in[3];
    float* out   = (float*)d_out;
    float* out_z = out;
    float* out_p = out + (size_t)L_N * B_N * D_N;

    __nv_bfloat16 *wh, *wl, *ch, *cl, *cth, *ctl;
    float* csq_p;
    cudaGetSymbolAddress((void**)&wh, g_W_hi);
    cudaGetSymbolAddress((void**)&wl, g_W_lo);
    cudaGetSymbolAddress((void**)&ch, g_cb_hi);
    cudaGetSymbolAddress((void**)&cl, g_cb_lo);
    cudaGetSymbolAddress((void**)&cth, g_cbT_hi);
    cudaGetSymbolAddress((void**)&ctl, g_cbT_lo);
    cudaGetSymbolAddress((void**)&csq_p, g_csq);

    cudaFuncSetAttribute(logits_kernel, cudaFuncAttributeMaxDynamicSharedMemorySize, SMEM_SZ);
    cudaFuncSetAttribute(zsoft_kernel,  cudaFuncAttributeMaxDynamicSharedMemorySize, SMEM_SZ);
    cudaFuncSetAttribute(whiten_kernel, cudaFuncAttributeMaxDynamicSharedMemorySize, SMEM_SZ);

    split_kernel<<<(D_N * D_N) / 256, 256>>>(W, wh, wl, D_N * D_N);
    split_kernel<<<(L_N * K_N * D_N) / 256, 256>>>(cbks, ch, cl, L_N * K_N * D_N);
    tsplit_kernel<<<dim3(K_N / 32, D_N / 32, L_N), dim3(32, 8)>>>(cbks);
    csq_kernel<<<(L_N * K_N) / 8, 256>>>(cbks);

    whiten_kernel<<<dim3(8, 256), 256, SMEM_SZ>>>(z0, wh, wl);
    for (int l = 0; l < L_N; l++) {
        logits_kernel<<<dim3(16, 256), 256, SMEM_SZ>>>(
            ch + (size_t)l * K_N * D_N, cl + (size_t)l * K_N * D_N,
            csq_p + l * K_N, tau);
        zsoft_kernel<<<dim3(8, 256), 256, SMEM_SZ>>>(
            cth + (size_t)l * D_N * K_N, ctl + (size_t)l * D_N * K_N,
            out_p + (size_t)l * B_N * K_N, out_z + (size_t)l * B_N * D_N);
    }
}

// round 10
// speedup vs baseline: 1.0556x; 1.0556x over previous
#include <cuda_runtime.h>
#include <cuda_bf16.h>
#include <cstdint>
#include <math.h>

#define B_N 32768
#define D_N 512
#define K_N 1024
#define L_N 4
#define THR 512

// smem (bytes). Rows padded to 80B -> conflict-free ldmatrix.
// A tile: 128x32 bf16 hi/lo single-buffered (register-staged).
// B tile: 128x32 bf16 hi/lo double-buffered (cp.async).
#define SA_HI  0
#define SA_LO  10240
#define SB0_HI 20480
#define SB0_LO 30720
#define SB1_HI 40960
#define SB1_LO 51200
#define SMISC  61440
#define SMEM_SZ 61952

__device__ float         g_zr   [(size_t)B_N * D_N];
__device__ __nv_bfloat16 g_zr_hi[(size_t)B_N * D_N];
__device__ __nv_bfloat16 g_zr_lo[(size_t)B_N * D_N];
__device__ __nv_bfloat16 g_cb_hi[(size_t)L_N * K_N * D_N];
__device__ __nv_bfloat16 g_cb_lo[(size_t)L_N * K_N * D_N];
__device__ __nv_bfloat16 g_cbT_hi[(size_t)L_N * D_N * K_N];
__device__ __nv_bfloat16 g_cbT_lo[(size_t)L_N * D_N * K_N];
__device__ __nv_bfloat16 g_W_hi[D_N * D_N];
__device__ __nv_bfloat16 g_W_lo[D_N * D_N];
__device__ float         g_csq[L_N * K_N];
__device__ float         g_E[(size_t)B_N * K_N];
__device__ float         g_Spart[(size_t)32 * B_N];

// ---------------- asm helpers ----------------
__device__ __forceinline__ uint32_t smem_u32(const void* p) {
    uint32_t a;
    asm("{ .reg .u64 t; cvta.to.shared.u64 t, %1; cvt.u32.u64 %0, t; }" : "=r"(a) : "l"(p));
    return a;
}
#define LDSM4(R0,R1,R2,R3,ADDR) \
    asm volatile("ldmatrix.sync.aligned.m8n8.x4.shared.b16 {%0,%1,%2,%3}, [%4];" \
        : "=r"(R0),"=r"(R1),"=r"(R2),"=r"(R3) : "r"(ADDR))
#define MMA(ACC,A,B0,B1) \
    asm volatile("mma.sync.aligned.m16n8k16.row.col.f32.bf16.bf16.f32 " \
        "{%0,%1,%2,%3},{%4,%5,%6,%7},{%8,%9},{%0,%1,%2,%3};" \
        : "+f"((ACC)[0]),"+f"((ACC)[1]),"+f"((ACC)[2]),"+f"((ACC)[3]) \
        : "r"((A)[0]),"r"((A)[1]),"r"((A)[2]),"r"((A)[3]),"r"(B0),"r"(B1))
#define CP16(DST,SRC) \
    asm volatile("cp.async.cg.shared.global [%0], [%1], 16;" :: "r"(DST), "l"(SRC))
#define CP_COMMIT() asm volatile("cp.async.commit_group;" ::: "memory")
#define CP_WAIT1()  asm volatile("cp.async.wait_group 1;" ::: "memory")
#define CP_WAIT0()  asm volatile("cp.async.wait_group 0;" ::: "memory")

__device__ __forceinline__ uint32_t pack2(float a, float b) {
    __nv_bfloat162 t = __floats2bfloat162_rn(a, b);
    return *(uint32_t*)&t;
}
__device__ __forceinline__ float bfr(float x) {
    return __bfloat162float(__float2bfloat16_rn(x));
}

// 3-pass bf16-split MMA over one K=32 chunk.
// A hi at SA_HI (+10240 lo); B hi at bBase (+10240 lo). Warp tile 32x32,
// wy,wx in 0..3 (CTA tile 128x128).
__device__ __forceinline__ void compute_chunk(float acc[2][4][4], uint32_t smb,
                                              uint32_t bBase, int wy, int wx, int lane) {
    #pragma unroll
    for (int ks = 0; ks < 2; ks++) {
        uint32_t aH[2][4], aL[2][4], bH[4][2], bL[4][2];
        #pragma unroll
        for (int i = 0; i < 2; i++) {
            uint32_t ar = smb + SA_HI + (uint32_t)(wy*32 + i*16 + (lane & 15))*80
                          + ks*32 + ((lane >> 4) << 4);
            LDSM4(aH[i][0],aH[i][1],aH[i][2],aH[i][3], ar);
            LDSM4(aL[i][0],aL[i][1],aL[i][2],aL[i][3], ar + 10240);
        }
        #pragma unroll
        for (int jj = 0; jj < 2; jj++) {
            uint32_t br = smb + bBase + (uint32_t)(wx*32 + jj*16 + (lane & 15))*80
                          + ks*32 + ((lane >> 4) << 4);
            uint32_t r0,r1,r2,r3;
            LDSM4(r0,r1,r2,r3, br);
            bH[jj*2][0]=r0; bH[jj*2][1]=r2; bH[jj*2+1][0]=r1; bH[jj*2+1][1]=r3;
            LDSM4(r0,r1,r2,r3, br + 10240);
            bL[jj*2][0]=r0; bL[jj*2][1]=r2; bL[jj*2+1][0]=r1; bL[jj*2+1][1]=r3;
        }
        #pragma unroll
        for (int i = 0; i < 2; i++)
            #pragma unroll
            for (int j = 0; j < 4; j++) {
                MMA(acc[i][j], aH[i], bH[j][0], bH[j][1]);
                MMA(acc[i][j], aH[i], bL[j][0], bL[j][1]);
                MMA(acc[i][j], aL[i], bH[j][0], bH[j][1]);
            }
    }
}

// B tile (128 rows x 32 cols bf16) hi+lo via cp.async; 512 threads.
__device__ __forceinline__ void cpasync_B(uint32_t smb, uint32_t bBase,
        const __nv_bfloat16* Bh, const __nv_bfloat16* Bl,
        int nb0, int strideB, int kc, int tid) {
    int row = tid >> 2, seg = tid & 3;
    uint32_t dst = smb + bBase + (uint32_t)row*80 + seg*16;
    size_t off = (size_t)(nb0 + row) * strideB + kc*32 + seg*8;
    CP16(dst,         (const char*)(Bh + off));
    CP16(dst + 10240, (const char*)(Bl + off));
}

// ---------------- prep kernels ----------------
__global__ void csq_kernel(const float* __restrict__ cb) {
    int warp = (blockIdx.x * blockDim.x + threadIdx.x) >> 5;
    int lane = threadIdx.x & 31;
    if (warp >= L_N * K_N) return;
    const float* row = cb + (size_t)warp * D_N;
    float s = 0.f;
    #pragma unroll 4
    for (int i = lane; i < D_N; i += 32) { float v = row[i]; s += v * v; }
    #pragma unroll
    for (int o = 16; o; o >>= 1) s += __shfl_xor_sync(0xffffffffu, s, o);
    if (lane == 0) g_csq[warp] = s;
}
__global__ void split_kernel(const float* __restrict__ src,
                             __nv_bfloat16* __restrict__ hi,
                             __nv_bfloat16* __restrict__ lo, int n) {
    int i = blockIdx.x * blockDim.x + threadIdx.x;
    if (i < n) {
        float x = src[i];
        __nv_bfloat16 h = __float2bfloat16_rn(x);
        hi[i] = h;
        lo[i] = __float2bfloat16_rn(x - __bfloat162float(h));
    }
}
__global__ void tsplit_kernel(const float* __restrict__ cb) {
    __shared__ float tile[32][33];
    int l = blockIdx.z;
    int k0 = blockIdx.x * 32, d0 = blockIdx.y * 32;
    int tx = threadIdx.x, ty = threadIdx.y;
    const float* src = cb + (size_t)l * K_N * D_N;
    for (int i = ty; i < 32; i += 8)
        tile[i][tx] = src[(size_t)(k0 + i) * D_N + d0 + tx];
    __syncthreads();
    __nv_bfloat16* th = g_cbT_hi + (size_t)l * D_N * K_N;
    __nv_bfloat16* tl = g_cbT_lo + (size_t)l * D_N * K_N;
    for (int i = ty; i < 32; i += 8) {
        float x = tile[tx][i];
        __nv_bfloat16 h = __float2bfloat16_rn(x);
        size_t o = (size_t)(d0 + i) * K_N + k0 + tx;
        th[o] = h;
        tl[o] = __float2bfloat16_rn(x - __bfloat162float(h));
    }
}

// ---------------- kernel A: logits -> E=exp((2s-csq)/tau) + partial row sums ----
// grid (8, 256), 512 thr. CTA tile 128(m) x 128(n), K=512.
__global__ void __launch_bounds__(THR, 1)
logits_kernel(const __nv_bfloat16* __restrict__ cbh,
              const __nv_bfloat16* __restrict__ cbl,
              const float* __restrict__ csq, const float* __restrict__ tau) {
    extern __shared__ __align__(16) char smem[];
    const uint32_t smb = smem_u32(smem);
    const int tid = threadIdx.x, lane = tid & 31, w = tid >> 5;
    const int wy = w >> 2, wx = w & 3;
    const int nb0 = blockIdx.x * 128, bm0 = blockIdx.y * 128;
    const float invtau = 1.0f / tau[0];
    float* csq_s = (float*)(smem + SMISC);
    if (tid < 128) csq_s[tid] = csq[nb0 + tid] * invtau;

    float acc[2][4][4];
    #pragma unroll
    for (int i = 0; i < 2; i++)
        #pragma unroll
        for (int j = 0; j < 4; j++)
            #pragma unroll
            for (int h = 0; h < 4; h++) acc[i][j][h] = 0.f;

    cpasync_B(smb, SB0_HI, cbh, cbl, nb0, D_N, 0, tid);
    CP_COMMIT();
    // register prefetch of A (chunk 0): one uint4 hi + lo per thread
    uint4 rah, ral;
    {
        int row = tid >> 2, seg = tid & 3;
        size_t o = ((size_t)(bm0 + row) * D_N + seg * 8) >> 3;
        rah = ((const uint4*)g_zr_hi)[o];
        ral = ((const uint4*)g_zr_lo)[o];
    }

    for (int kc = 0; kc < 16; kc++) {
        __syncthreads();   // frees SA + target B buffer from compute(kc-1)
        if (kc + 1 < 16) {
            cpasync_B(smb, ((kc + 1) & 1) ? SB1_HI : SB0_HI, cbh, cbl, nb0, D_N, kc + 1, tid);
            CP_COMMIT();
        }
        {
            int row = tid >> 2, seg = tid & 3;
            *(uint4*)(smem + SA_HI + row * 80 + seg * 16) = rah;
            *(uint4*)(smem + SA_LO + row * 80 + seg * 16) = ral;
        }
        if (kc + 1 < 16) CP_WAIT1(); else CP_WAIT0();
        __syncthreads();
        if (kc + 1 < 16) {
            int row = tid >> 2, seg = tid & 3;
            size_t o = ((size_t)(bm0 + row) * D_N + (kc + 1) * 32 + seg * 8) >> 3;
            rah = ((const uint4*)g_zr_hi)[o];
            ral = ((const uint4*)g_zr_lo)[o];
        }
        compute_chunk(acc, smb, (kc & 1) ? SB1_HI : SB0_HI, wy, wx, lane);
    }

    // epilogue: E = exp(2s/tau - csq/tau), partial row sums (deterministic)
    const float c2 = 2.0f * invtau;
    #pragma unroll
    for (int i = 0; i < 2; i++) {
        #pragma unroll
        for (int h = 0; h < 2; h++) {
            int r = bm0 + wy * 32 + i * 16 + (lane >> 2) + h * 8;
            float s = 0.f;
            #pragma unroll
            for (int j = 0; j < 4; j++) {
                int cl = wx * 32 + j * 8 + ((lane & 3) << 1);
                float e0 = __expf(fmaf(acc[i][j][h * 2],     c2, -csq_s[cl]));
                float e1 = __expf(fmaf(acc[i][j][h * 2 + 1], c2, -csq_s[cl + 1]));
                s += e0 + e1;
                *(float2*)&g_E[(size_t)r * K_N + nb0 + cl] = make_float2(e0, e1);
            }
            s += __shfl_xor_sync(0xffffffffu, s, 1);
            s += __shfl_xor_sync(0xffffffffu, s, 2);
            if ((lane & 3) == 0)
                g_Spart[(size_t)(blockIdx.x * 4 + wx) * B_N + r] = s;
        }
    }
}

// ---------------- kernel B (whiten / zsoft) ----------------
// mode 0: srcA=z0 (K=512, NC=16), B=W -> g_zr(+hi/lo). grid (4,256).
// mode 1: srcA=g_E (K=1024, NC=32), normalize, bx==0 writes p; B=cbT ->
//         out_z, g_zr -= z, re-split. grid (4,256).
__global__ void __launch_bounds__(THR, 1)
out_gemm_kernel(const float* __restrict__ srcA, int strideA, int NC,
                const __nv_bfloat16* __restrict__ Bh, const __nv_bfloat16* __restrict__ Bl,
                int strideB, float* __restrict__ pout, float* __restrict__ out_z, int mode) {
    extern __shared__ __align__(16) char smem[];
    const uint32_t smb = smem_u32(smem);
    const int tid = threadIdx.x, lane = tid & 31, w = tid >> 5;
    const int wy = w >> 2, wx = w & 3;
    const int nb0 = blockIdx.x * 128, bm0 = blockIdx.y * 128;
    const float* A_src = mode ? g_E : srcA;
    float* invs = (float*)(smem + SMISC);
    if (mode && tid < 128) {
        float s = 0.f;
        #pragma unroll
        for (int p = 0; p < 32; p++) s += g_Spart[(size_t)p * B_N + bm0 + tid];
        invs[tid] = 1.0f / s;
    }
    float* pw = (mode && blockIdx.x == 0) ? pout : nullptr;

    float acc[2][4][4];
    #pragma unroll
    for (int i = 0; i < 2; i++)
        #pragma unroll
        for (int j = 0; j < 4; j++)
            #pragma unroll
            for (int h = 0; h < 4; h++) acc[i][j][h] = 0.f;

    cpasync_B(smb, SB0_HI, Bh, Bl, nb0, strideB, 0, tid);
    CP_COMMIT();
    float4 raf[2];
    #pragma unroll
    for (int i = 0; i < 2; i++) {
        int idx = tid + i * THR, row = idx >> 3, seg = idx & 7;
        raf[i] = *(const float4*)&A_src[(size_t)(bm0 + row) * strideA + seg * 4];
    }

    for (int kc = 0; kc < NC; kc++) {
        __syncthreads();
        if (kc + 1 < NC) {
            cpasync_B(smb, ((kc + 1) & 1) ? SB1_HI : SB0_HI, Bh, Bl, nb0, strideB, kc + 1, tid);
            CP_COMMIT();
        }
        #pragma unroll
        for (int i = 0; i < 2; i++) {
            int idx = tid + i * THR, row = idx >> 3, seg = idx & 7;
            float4 v = raf[i];
            if (mode) {
                float s = invs[row];
                v.x *= s; v.y *= s; v.z *= s; v.w *= s;
                if (pw)
                    *(float4*)&pw[(size_t)(bm0 + row) * K_N + kc * 32 + seg * 4] = v;
            }
            float hx = bfr(v.x), hy = bfr(v.y), hz = bfr(v.z), hw = bfr(v.w);
            *(uint2*)(smem + SA_HI + row * 80 + seg * 8) =
                make_uint2(pack2(hx, hy), pack2(hz, hw));
            *(uint2*)(smem + SA_LO + row * 80 + seg * 8) =
                make_uint2(pack2(v.x - hx, v.y - hy), pack2(v.z - hz, v.w - hw));
        }
        if (kc + 1 < NC) CP_WAIT1(); else CP_WAIT0();
        __syncthreads();
        if (kc + 1 < NC) {
            #pragma unroll
            for (int i = 0; i < 2; i++) {
                int idx = tid + i * THR, row = idx >> 3, seg = idx & 7;
                raf[i] = *(const float4*)&A_src[(size_t)(bm0 + row) * strideA
                                                + (kc + 1) * 32 + seg * 4];
            }
        }
        compute_chunk(acc, smb, (kc & 1) ? SB1_HI : SB0_HI, wy, wx, lane);
    }

    #pragma unroll
    for (int i = 0; i < 2; i++)
        #pragma unroll
        for (int j = 0; j < 4; j++)
            #pragma unroll
            for (int h = 0; h < 2; h++) {
                int r = bm0 + wy * 32 + i * 16 + (lane >> 2) + h * 8;
                int col = nb0 + wx * 32 + j * 8 + ((lane & 3) << 1);
                size_t g = (size_t)r * D_N + col;
                float v0 = acc[i][j][h * 2], v1 = acc[i][j][h * 2 + 1];
                float2 nr;
                if (mode) {
                    float2 old = *(const float2*)&g_zr[g];
                    *(float2*)&out_z[g] = make_float2(v0, v1);
                    nr = make_float2(old.x - v0, old.y - v1);
                } else {
                    nr = make_float2(v0, v1);
                }
                *(float2*)&g_zr[g] = nr;
                float hx = bfr(nr.x), hy = bfr(nr.y);
                *(uint32_t*)&g_zr_hi[g] = pack2(hx, hy);
                *(uint32_t*)&g_zr_lo[g] = pack2(nr.x - hx, nr.y - hy);
            }
}

// ---------------- launch ----------------
extern "C" void kernel_launch(void* const* d_in, const int* in_sizes, int n_in,
                              void* d_out, int out_size)
{
    const float* z0   = (const float*)d_in[0];
    const float* tau  = (const float*)d_in[1];
    const float* W    = (const float*)d_in[2];
    const float* cbks = (const float*)d_in[3];
    float* out   = (float*)d_out;
    float* out_z = out;
    float* out_p = out + (size_t)L_N * B_N * D_N;

    __nv_bfloat16 *wh, *wl, *ch, *cl, *cth, *ctl;
    float* csq_p;
    cudaGetSymbolAddress((void**)&wh, g_W_hi);
    cudaGetSymbolAddress((void**)&wl, g_W_lo);
    cudaGetSymbolAddress((void**)&ch, g_cb_hi);
    cudaGetSymbolAddress((void**)&cl, g_cb_lo);
    cudaGetSymbolAddress((void**)&cth, g_cbT_hi);
    cudaGetSymbolAddress((void**)&ctl, g_cbT_lo);
    cudaGetSymbolAddress((void**)&csq_p, g_csq);

    cudaFuncSetAttribute(logits_kernel, cudaFuncAttributeMaxDynamicSharedMemorySize, SMEM_SZ);
    cudaFuncSetAttribute(out_gemm_kernel, cudaFuncAttributeMaxDynamicSharedMemorySize, SMEM_SZ);

    split_kernel<<<(D_N * D_N) / 256, 256>>>(W, wh, wl, D_N * D_N);
    split_kernel<<<(L_N * K_N * D_N) / 256, 256>>>(cbks, ch, cl, L_N * K_N * D_N);
    tsplit_kernel<<<dim3(K_N / 32, D_N / 32, L_N), dim3(32, 8)>>>(cbks);
    csq_kernel<<<(L_N * K_N) / 8, 256>>>(cbks);

    // whitening: g_zr = z0 @ W^T
    out_gemm_kernel<<<dim3(4, 256), THR, SMEM_SZ>>>(z0, D_N, 16, wh, wl, D_N,
                                                    nullptr, nullptr, 0);
    for (int l = 0; l < L_N; l++) {
        logits_kernel<<<dim3(8, 256), THR, SMEM_SZ>>>(
            ch + (size_t)l * K_N * D_N, cl + (size_t)l * K_N * D_N,
            csq_p + l * K_N, tau);
        out_gemm_kernel<<<dim3(4, 256), THR, SMEM_SZ>>>(
            nullptr, K_N, 32,
            cth + (size_t)l * D_N * K_N, ctl + (size_t)l * D_N * K_N, K_N,
            out_p + (size_t)l * B_N * K_N, out_z + (size_t)l * B_N * D_N, 1);
    }
}